// round 12
// baseline (speedup 1.0000x reference)
#include <cuda_runtime.h>
#include <cuda_fp16.h>

#define OH 121
#define NIMG 8

// ---------------- smem layout (b32 word offsets), per 256-thread CTA ------
// A frags (fp16): 4 mtiles x 20 k16-groups x 32 lanes x 4 words = 10240 words (40KB)
#define BB_OFF    10240      // 3 B-chunk buffers x 4096 words (16KB each)
#define THR_OFF   22528      // thr[64] fp32
#define SM_WORDS  22592
#define SMEM_BYTES (SM_WORDS * 4)    // 90368 B -> 2 CTAs/SM

// ---------------- device scratch ----------------
// B operands fp16, K32-chunk frag order (R8 layout)
__device__ __align__(16) __half g_Bls[256 * 256];  // S
__device__ __align__(16) __half g_Bh1[64 * 128];   // W1
__device__ __align__(16) __half g_Bh2[128 * 64];   // W2
__device__ __align__(16) __half g_Bh3[64 * 32];    // W3
__device__ __align__(16) __half g_By [64 * 256];   // Dict
__device__ __align__(16) __half g_Bxp[256 * 64];   // Dict^T
__device__ float g_XP[64 * NIMG * 128 * 128];      // x_pred, [d][img][pix]
__device__ uint2 g_YC[2048 * 4096];                // y/c fp16 frag-order, per CTA

// ---------------- helpers ----------------
static __device__ __forceinline__ float r16(float v) {
    return __half2float(__float2half_rn(v));
}
static __device__ __forceinline__ unsigned h2u(__half2 h) {
    return *reinterpret_cast<unsigned*>(&h);
}
static __device__ __forceinline__ __half2 u2h(unsigned u) {
    return *reinterpret_cast<__half2*>(&u);
}
static __device__ __forceinline__ float softthr(float v, float t) {
    float r = fmaxf(fabsf(v) - t, 0.0f);
    float s = (v > 0.0f) ? 1.0f : ((v < 0.0f) ? -1.0f : 0.0f);
    return s * r;
}
static __device__ __forceinline__ void cpasync16(void* dst_sm, const void* src) {
    unsigned d = (unsigned)__cvta_generic_to_shared(dst_sm);
    asm volatile("cp.async.cg.shared.global [%0], [%1], 16;" :: "r"(d), "l"(src));
}
static __device__ __forceinline__ void mma16(float* d, const unsigned* a,
                                             unsigned b0, unsigned b1) {
    asm volatile(
        "mma.sync.aligned.m16n8k16.row.col.f32.f16.f16.f32 "
        "{%0,%1,%2,%3}, {%4,%5,%6,%7}, {%8,%9}, {%0,%1,%2,%3};"
        : "+f"(d[0]), "+f"(d[1]), "+f"(d[2]), "+f"(d[3])
        : "r"(a[0]), "r"(a[1]), "r"(a[2]), "r"(a[3]), "r"(b0), "r"(b1));
}

// A fragment b32-word address for element (r in 0..63, c in 0..319); c even
static __device__ __forceinline__ int af_word(int r, int c) {
    return (((r >> 4) * 20 + (c >> 4)) * 32 + ((r & 7) << 2) + ((c & 7) >> 1)) * 4
           + ((r >> 3) & 1) + (((c >> 3) & 1) << 1);
}
static __device__ __forceinline__ int af_half(int r, int c) {
    return af_word(r, c & ~1) * 2 + (c & 1);
}
// B fragment half-index in gmem, K32-chunk layout, stage width N: elem B[k][n]
static __device__ __forceinline__ int fidx_h(int N, int k, int n) {
    int NT = N >> 5;
    int chunk = k >> 5, s = (k >> 4) & 1, kk = k & 15;
    int tg = (kk >> 1) & 3, regk = (kk >> 3) & 1;
    int Nq = N >> 2, ns = n / Nq, rem = n % Nq, nt = rem >> 3, g = rem & 7;
    int lane = (g << 2) | tg;
    int word;
    if (NT >= 2) {
        int w = nt * 2 + regk, p = w >> 2, j = w & 3;
        word = chunk * 16 * N + (s * 4 + ns) * (NT * 64) + p * 128 + lane * 4 + j;
    } else {
        word = chunk * 512 + (s * 4 + ns) * 64 + lane * 2 + regk;
    }
    return word * 2 + (k & 1);
}
// yc uint2 index for epilogue element group at (r, c) [N=256 frag mapping]
// inner index (r&7)*4 + tg == lane -> coalesced 256B segments per warp
static __device__ __forceinline__ int yc_idx(int r, int c) {
    return ((((r >> 4) * 4 + (c >> 6)) * 8 + ((c >> 3) & 7)) * 32)
           + ((r & 7) * 4 + ((c >> 1) & 3));
}

// ---------------- warp-tiled fp16 GEMM stage -----------------------------
// D[64][N] = A_frag_sm[64][K] @ B_frag_gmem[K][N], fp32 accum.
// 8 warps = 2 m-halves x 4 n-slices. K32 chunks, 3 rotating 16KB buffers,
// depth-2 cp.async prefetch, one barrier per chunk + trailing barrier.
template <int N, int K, int AB16, bool PE, class Epi>
static __device__ __forceinline__ void gemm_stage(
    float* sm, const __half* __restrict__ gB, int tid, Epi epi)
{
    constexpr int NT  = N / 32;
    constexpr int NT2 = (NT >= 2) ? NT / 2 : 1;
    constexpr int NCH = K / 32;
    constexpr int P   = 4 * N;                   // uint4 pieces per chunk
    const int wid = tid >> 5, lane = tid & 31;
    const int g = lane >> 2, tg = lane & 3;
    const int mt0  = (wid & 1) * 2;
    const int ns   = wid >> 1;
    const int ncol = ns * (N / 4);

    float acc[2][NT][4];
#pragma unroll
    for (int a = 0; a < 2; a++)
#pragma unroll
        for (int b = 0; b < NT; b++)
#pragma unroll
            for (int q = 0; q < 4; q++) acc[a][b][q] = 0.0f;

    const uint4* gB4 = (const uint4*)gB;
    uint4* bb4 = (uint4*)(sm + BB_OFF);
    const uint4* A4 = (const uint4*)sm;

    auto load_chunk = [&](int c) {
        const uint4* src = gB4 + (size_t)c * P;
        uint4* dst = bb4 + (c % 3) * 1024;
#pragma unroll
        for (int p0 = 0; p0 < P; p0 += 256) {
            int p = p0 + tid;
            if ((P % 256 == 0) || p < P) cpasync16(dst + p, src + p);
        }
        asm volatile("cp.async.commit_group;");
    };

    load_chunk(0);
    if (NCH > 1) load_chunk(1);

    for (int c = 0; c < NCH; c++) {
        if (c + 1 < NCH) asm volatile("cp.async.wait_group 1;");
        else             asm volatile("cp.async.wait_group 0;");
        __syncthreads();                 // chunk c visible; buf (c+2)%3 free
        if (c + 2 < NCH) load_chunk(c + 2);
        const uint4* bbuf4 = bb4 + (c % 3) * 1024;
#pragma unroll
        for (int s = 0; s < 2; s++) {
            const int q = AB16 + c * 2 + s;
            uint4 av[2];
#pragma unroll
            for (int mt = 0; mt < 2; mt++)
                av[mt] = A4[((mt0 + mt) * 20 + q) * 32 + lane];
            unsigned bw[2 * NT];
            if (NT >= 2) {
                uint4* bv = (uint4*)bw;
#pragma unroll
                for (int p = 0; p < NT2; p++)
                    bv[p] = bbuf4[(s * 4 + ns) * (NT * 16) + p * 32 + lane];
            } else {
                uint2 b2 = ((const uint2*)bbuf4)[(s * 4 + ns) * 32 + lane];
                bw[0] = b2.x; bw[1] = b2.y;
            }
#pragma unroll
            for (int nt = 0; nt < NT; nt++) {
                mma16(acc[0][nt], (const unsigned*)&av[0], bw[nt * 2], bw[nt * 2 + 1]);
                mma16(acc[1][nt], (const unsigned*)&av[1], bw[nt * 2], bw[nt * 2 + 1]);
            }
        }
    }
    if (PE) __syncthreads();             // in-place: all reads done before writes
#pragma unroll
    for (int mt = 0; mt < 2; mt++)
#pragma unroll
        for (int nt = 0; nt < NT; nt++)
            epi((mt0 + mt) * 16 + g, ncol + nt * 8 + tg * 2, acc[mt][nt]);
    __syncthreads();                     // publish epi writes; protect B bufs
}

// ---------------- main fused kernel (256 thr, 64 patches/CTA) ------------
__global__ void __launch_bounds__(256, 2) lista_mma(
    const float* __restrict__ x,  const float* __restrict__ cp,
    const float* __restrict__ wp,
    const float* __restrict__ b1, const float* __restrict__ b2,
    const float* __restrict__ b3, const float* __restrict__ W4,
    const float* __restrict__ b4)
{
    extern __shared__ float sm[];
    __half2* smh2 = (__half2*)sm;
    __half*  smh  = (__half*)sm;
    const int tid = threadIdx.x;
    const int img = blockIdx.z;
    const int pr0 = blockIdx.y * 8, pc0 = blockIdx.x * 8;
    const float cv = cp[0], wv = wp[0];
    const float* xi = x + img * 16384;
    float* thr = sm + THR_OFF;
    uint2* ycg = g_YC + ((size_t)(img * 256 + blockIdx.y * 16 + blockIdx.x)) * 4096;

    // ---- U -> A frag cols [256,320), fp16, zero-padded outside image ----
    for (int idx = tid; idx < 4096; idx += 256) {
        int m = idx >> 6, d = idx & 63;
        int pr = pr0 + (m >> 3), pc = pc0 + (m & 7);
        float v = (pr < OH && pc < OH) ? xi[(pr + (d >> 3)) * 128 + pc + (d & 7)] : 0.0f;
        smh[af_half(m, 256 + d)] = __float2half_rn(v);
    }
    // (first barrier inside gemm_stage publishes U)

    // ---- h1 = relu(U@W1+b1) -> cols [0,128) ----
    gemm_stage<128, 64, 16, false>(sm, g_Bh1, tid, [&](int r, int c, float* d) {
        float bb0 = __ldg(b1 + c), bb1 = __ldg(b1 + c + 1);
        smh2[af_word(r, c)]     = __floats2half2_rn(fmaxf(d[0] + bb0, 0.0f),
                                                    fmaxf(d[1] + bb1, 0.0f));
        smh2[af_word(r + 8, c)] = __floats2half2_rn(fmaxf(d[2] + bb0, 0.0f),
                                                    fmaxf(d[3] + bb1, 0.0f));
    });

    // ---- h2 = relu(h1@W2+b2) -> cols [128,192) ----
    gemm_stage<64, 128, 0, false>(sm, g_Bh2, tid, [&](int r, int c, float* d) {
        float bb0 = __ldg(b2 + c), bb1 = __ldg(b2 + c + 1);
        int cc = 128 + c;
        smh2[af_word(r, cc)]     = __floats2half2_rn(fmaxf(d[0] + bb0, 0.0f),
                                                     fmaxf(d[1] + bb1, 0.0f));
        smh2[af_word(r + 8, cc)] = __floats2half2_rn(fmaxf(d[2] + bb0, 0.0f),
                                                     fmaxf(d[3] + bb1, 0.0f));
    });

    // ---- h3 = relu(h2@W3+b3) -> cols [192,224) ----
    gemm_stage<32, 64, 8, false>(sm, g_Bh3, tid, [&](int r, int c, float* d) {
        float bb0 = __ldg(b3 + c), bb1 = __ldg(b3 + c + 1);
        int cc = 192 + c;
        smh2[af_word(r, cc)]     = __floats2half2_rn(fmaxf(d[0] + bb0, 0.0f),
                                                     fmaxf(d[1] + bb1, 0.0f));
        smh2[af_word(r + 8, cc)] = __floats2half2_rn(fmaxf(d[2] + bb0, 0.0f),
                                                     fmaxf(d[3] + bb1, 0.0f));
    });

    // ---- thr[m] = (h3[m]@W4 + b4)/c  (h3 published by stage's trailing bar)
    if (tid < 64) {
        float a = b4[0];
#pragma unroll
        for (int j = 0; j < 32; j++)
            a = fmaf(__half2float(smh[af_half(tid, 192 + j)]), r16(__ldg(W4 + j)), a);
        thr[tid] = a / cv;
    }
    // (published by y-stage's first barrier; read only in y's epilogue)

    // ---- y = U@Dict ; yc = fp16(y/c) -> gmem frag scratch ; z0 = soft(y,thr)
    gemm_stage<256, 64, 16, false>(sm, g_By, tid, [&](int r, int c, float* d) {
        float t0 = thr[r], t1 = thr[r + 8];
        uint2 y2;
        y2.x = h2u(__floats2half2_rn(d[0] / cv, d[1] / cv));
        y2.y = h2u(__floats2half2_rn(d[2] / cv, d[3] / cv));
        ycg[yc_idx(r, c)] = y2;
        smh2[af_word(r, c)]     = __floats2half2_rn(softthr(d[0], t0), softthr(d[1], t0));
        smh2[af_word(r + 8, c)] = __floats2half2_rn(softthr(d[2], t1), softthr(d[3], t1));
    });

    // ---- 7x LISTA: z = soft(z@S + y/c, thr), K=256 (y/c from gmem) ----
    for (int it = 0; it < 7; it++) {
        gemm_stage<256, 256, 0, true>(sm, g_Bls, tid, [&](int r, int c, float* d) {
            float t0 = thr[r], t1 = thr[r + 8];
            uint2 y2 = __ldg(&ycg[yc_idx(r, c)]);
            __half2 ya = u2h(y2.x), yb = u2h(y2.y);
            float v0 = d[0] + __low2float(ya),  v1 = d[1] + __high2float(ya);
            float v2 = d[2] + __low2float(yb),  v3 = d[3] + __high2float(yb);
            smh2[af_word(r, c)]     = __floats2half2_rn(softthr(v0, t0), softthr(v1, t0));
            smh2[af_word(r + 8, c)] = __floats2half2_rn(softthr(v2, t1), softthr(v3, t1));
        });
    }

    // ---- x_pred = clip(z@Dict^T, 0, 1)*w -> g_XP ([d][img][pix] planes) ----
    gemm_stage<64, 256, 0, false>(sm, g_Bxp, tid, [&](int r, int c, float* d) {
        int pr = pr0 + (r >> 3), pc = pc0 + (r & 7);
        if (pr < OH && pc < OH) {
            int gp = img * 16384 + pr * 128 + pc;
            g_XP[(size_t)c * 131072 + gp]       = fminf(fmaxf(d[0], 0.0f), 1.0f) * wv;
            g_XP[(size_t)(c + 1) * 131072 + gp] = fminf(fmaxf(d[1], 0.0f), 1.0f) * wv;
        }
        int r2 = r + 8;
        int pr2 = pr0 + (r2 >> 3), pc2 = pc0 + (r2 & 7);
        if (pr2 < OH && pc2 < OH) {
            int gp2 = img * 16384 + pr2 * 128 + pc2;
            g_XP[(size_t)c * 131072 + gp2]       = fminf(fmaxf(d[2], 0.0f), 1.0f) * wv;
            g_XP[(size_t)(c + 1) * 131072 + gp2] = fminf(fmaxf(d[3], 0.0f), 1.0f) * wv;
        }
    });
}

// ---------------- prep: S (fp16, K32-chunk frag order) ----------------
__global__ void prep_S(const float* __restrict__ Dict, const float* __restrict__ cp) {
    int k = blockIdx.x, n = threadIdx.x;
    float c = cp[0], s = 0.0f;
#pragma unroll 8
    for (int r = 0; r < 64; r++)
        s = fmaf(r16(Dict[r * 256 + k]), r16(Dict[r * 256 + n]), s);
    g_Bls[fidx_h(256, k, n)] = __float2half_rn((k == n ? 1.0f : 0.0f) - s / c);
}

// ---------------- prep: all other B operands ----------------
__global__ void prep_misc(const float* __restrict__ Dict, const float* __restrict__ W1,
                          const float* __restrict__ W2, const float* __restrict__ W3) {
    int idx = blockIdx.x * 256 + threadIdx.x;     // 64 blocks -> 16384 ids
    if (idx < 16384) {
        int kk = idx >> 8, n = idx & 255;
        g_By[fidx_h(256, kk, n)] = __float2half_rn(Dict[idx]);
        int k2 = idx >> 6, n2 = idx & 63;
        g_Bxp[fidx_h(64, k2, n2)] = __float2half_rn(Dict[n2 * 256 + k2]);
    }
    if (idx < 8192) {
        g_Bh1[fidx_h(128, idx >> 7, idx & 127)] = __float2half_rn(W1[idx]);
        g_Bh2[fidx_h(64,  idx >> 6, idx & 63)]  = __float2half_rn(W2[idx]);
    }
    if (idx < 2048)
        g_Bh3[fidx_h(32, idx >> 5, idx & 31)] = __float2half_rn(W3[idx]);
}

// ---------------- finalize: coalesced gather fold + analytic denominator ----
__global__ void finalize_kernel(float* __restrict__ out, const float* __restrict__ wp) {
    int idx = blockIdx.x * 256 + threadIdx.x;
    int img = idx >> 14, i = (idx >> 7) & 127, j = idx & 127;
    int base = img * 16384;
    float s = 0.0f;
#pragma unroll
    for (int di = 0; di < 8; di++) {
        int pr = i - di;
        if (pr < 0 || pr >= OH) continue;
#pragma unroll
        for (int dj = 0; dj < 8; dj++) {
            int pc = j - dj;
            if (pc < 0 || pc >= OH) continue;
            s += g_XP[(size_t)(di * 8 + dj) * 131072 + base + pr * 128 + pc];
        }
    }
    int ci = min(min(i + 1, 8), 128 - i);
    int cj = min(min(j + 1, 8), 128 - j);
    out[idx] = s / (wp[0] * (float)(ci * cj));
}

// ---------------- launch ----------------
extern "C" void kernel_launch(void* const* d_in, const int* in_sizes, int n_in,
                              void* d_out, int out_size) {
    const float* x    = (const float*)d_in[0];
    const float* Dict = (const float*)d_in[1];
    const float* c    = (const float*)d_in[2];
    const float* w    = (const float*)d_in[3];
    const float* W1   = (const float*)d_in[4];
    const float* b1   = (const float*)d_in[5];
    const float* W2   = (const float*)d_in[6];
    const float* b2   = (const float*)d_in[7];
    const float* W3   = (const float*)d_in[8];
    const float* b3   = (const float*)d_in[9];
    const float* W4   = (const float*)d_in[10];
    const float* b4   = (const float*)d_in[11];
    float* out = (float*)d_out;

    cudaFuncSetAttribute(lista_mma, cudaFuncAttributeMaxDynamicSharedMemorySize, SMEM_BYTES);

    prep_S<<<256, 256>>>(Dict, c);
    prep_misc<<<64, 256>>>(Dict, W1, W2, W3);
    lista_mma<<<dim3(16, 16, NIMG), 256, SMEM_BYTES>>>(x, c, w, b1, b2, b3, W4, b4);
    finalize_kernel<<<512, 256>>>(out, w);
}

// round 15
// speedup vs baseline: 1.0197x; 1.0197x over previous
#include <cuda_runtime.h>
#include <cuda_fp16.h>

#define OH 121
#define NIMG 8

// ---------------- smem layout (b32 word offsets), per 256-thread CTA ------
// A frags (fp16): 4 mtiles x 20 k16-groups x 32 lanes x 4 words = 10240 words (40KB)
#define BB_OFF    10240      // 5 B-chunk buffers x 2048 words (8KB each)
#define YC_OFF    20480      // y/c in frag order: 4096 uint2 = 8192 words (32KB)
#define THR_OFF   28672      // thr[64] fp32
#define SM_WORDS  28736
#define SMEM_BYTES (SM_WORDS * 4)    // 114944 B -> 2 CTAs/SM (229888 <= 232448)

// ---------------- device scratch: B operands fp16, K16-chunk frag order ---
__device__ __align__(16) __half g_Bls[256 * 256];  // S
__device__ __align__(16) __half g_Bh1[64 * 128];   // W1
__device__ __align__(16) __half g_Bh2[128 * 64];   // W2
__device__ __align__(16) __half g_Bh3[64 * 32];    // W3
__device__ __align__(16) __half g_By [64 * 256];   // Dict
__device__ __align__(16) __half g_Bxp[256 * 64];   // Dict^T
__device__ float g_XP[64 * NIMG * 128 * 128];      // x_pred, [d][img][pix]

// ---------------- helpers ----------------
static __device__ __forceinline__ float r16(float v) {
    return __half2float(__float2half_rn(v));
}
static __device__ __forceinline__ unsigned h2u(__half2 h) {
    return *reinterpret_cast<unsigned*>(&h);
}
static __device__ __forceinline__ __half2 u2h(unsigned u) {
    return *reinterpret_cast<__half2*>(&u);
}
static __device__ __forceinline__ float softthr(float v, float t) {
    float r = fmaxf(fabsf(v) - t, 0.0f);
    float s = (v > 0.0f) ? 1.0f : ((v < 0.0f) ? -1.0f : 0.0f);
    return s * r;
}
static __device__ __forceinline__ void cpasync16(void* dst_sm, const void* src) {
    unsigned d = (unsigned)__cvta_generic_to_shared(dst_sm);
    asm volatile("cp.async.cg.shared.global [%0], [%1], 16;" :: "r"(d), "l"(src));
}
static __device__ __forceinline__ void mma16(float* d, const unsigned* a,
                                             unsigned b0, unsigned b1) {
    asm volatile(
        "mma.sync.aligned.m16n8k16.row.col.f32.f16.f16.f32 "
        "{%0,%1,%2,%3}, {%4,%5,%6,%7}, {%8,%9}, {%0,%1,%2,%3};"
        : "+f"(d[0]), "+f"(d[1]), "+f"(d[2]), "+f"(d[3])
        : "r"(a[0]), "r"(a[1]), "r"(a[2]), "r"(a[3]), "r"(b0), "r"(b1));
}

// A fragment b32-word address for element (r in 0..63, c in 0..319); c even
static __device__ __forceinline__ int af_word(int r, int c) {
    return (((r >> 4) * 20 + (c >> 4)) * 32 + ((r & 7) << 2) + ((c & 7) >> 1)) * 4
           + ((r >> 3) & 1) + (((c >> 3) & 1) << 1);
}
static __device__ __forceinline__ int af_half(int r, int c) {
    return af_word(r, c & ~1) * 2 + (c & 1);
}
// B fragment half-index in gmem, K16-chunk layout, stage width N: elem B[k][n]
static __device__ __forceinline__ int fidx_h(int N, int k, int n) {
    int NT = N >> 5;
    int chunk = k >> 4, kk = k & 15;
    int tg = (kk >> 1) & 3, regk = (kk >> 3) & 1;
    int Nq = N >> 2, ns = n / Nq, rem = n % Nq, nt = rem >> 3, g = rem & 7;
    int lane = (g << 2) | tg;
    int word;
    if (NT >= 2) {
        int w = nt * 2 + regk, p = w >> 2, j = w & 3;
        word = chunk * 8 * N + ns * (NT * 64) + (p * 32 + lane) * 4 + j;
    } else {
        word = chunk * 256 + ns * 64 + lane * 2 + regk;
    }
    return word * 2 + (k & 1);
}
// yc uint2 index for epilogue element pair at (r, c) [N=256 frag mapping]
static __device__ __forceinline__ int yc_idx(int r, int c) {
    return ((((r >> 4) * 4 + (c >> 6)) * 8 + ((c >> 3) & 7)) * 32)
           + ((r & 7) * 4 + ((c >> 1) & 3));
}

// ---------------- warp-tiled fp16 GEMM stage -----------------------------
// D[64][N] = A_frag_sm[64][K] @ B_frag_gmem[K][N], fp32 accum.
// 8 warps = 2 m-halves x 4 n-slices. K16 chunks, 5 rotating 8KB buffers,
// depth-4 cp.async prefetch, one barrier per chunk + trailing barrier.
template <int N, int K, int AB16, bool PE, class Epi>
static __device__ __forceinline__ void gemm_stage(
    float* sm, const __half* __restrict__ gB, int tid, Epi epi)
{
    constexpr int NT  = N / 32;
    constexpr int NT2 = (NT >= 2) ? NT / 2 : 1;
    constexpr int NCH = K / 16;
    constexpr int P   = 2 * N;                   // uint4 pieces per chunk
    const int wid = tid >> 5, lane = tid & 31;
    const int g = lane >> 2, tg = lane & 3;
    const int mt0  = (wid & 1) * 2;
    const int ns   = wid >> 1;
    const int ncol = ns * (N / 4);

    float acc[2][NT][4];
#pragma unroll
    for (int a = 0; a < 2; a++)
#pragma unroll
        for (int b = 0; b < NT; b++)
#pragma unroll
            for (int q = 0; q < 4; q++) acc[a][b][q] = 0.0f;

    const uint4* gB4 = (const uint4*)gB;
    uint4* bb4 = (uint4*)(sm + BB_OFF);
    const uint4* A4 = (const uint4*)sm;

    auto load_chunk = [&](int c) {
        const uint4* src = gB4 + (size_t)c * P;
        uint4* dst = bb4 + (c % 5) * 512;
#pragma unroll
        for (int p0 = 0; p0 < P; p0 += 256) {
            int p = p0 + tid;
            if ((P % 256 == 0) || p < P) cpasync16(dst + p, src + p);
        }
        asm volatile("cp.async.commit_group;");
    };

    load_chunk(0); load_chunk(1); load_chunk(2); load_chunk(3);

    for (int c = 0; c < NCH; c++) {
        if (c + 4 <= NCH)      asm volatile("cp.async.wait_group 3;");
        else if (c + 3 == NCH) asm volatile("cp.async.wait_group 2;");
        else if (c + 2 == NCH) asm volatile("cp.async.wait_group 1;");
        else                   asm volatile("cp.async.wait_group 0;");
        __syncthreads();                 // chunk c visible; buf (c+4)%5 free
        if (c + 4 < NCH) load_chunk(c + 4);
        const uint4* bbuf4 = bb4 + (c % 5) * 512;
        {
            const int q = AB16 + c;      // one k16 step per chunk
            uint4 av[2];
#pragma unroll
            for (int mt = 0; mt < 2; mt++)
                av[mt] = A4[((mt0 + mt) * 20 + q) * 32 + lane];
            unsigned bw[2 * NT];
            if (NT >= 2) {
                uint4* bv = (uint4*)bw;
#pragma unroll
                for (int p = 0; p < NT2; p++)
                    bv[p] = bbuf4[ns * (NT * 16) + p * 32 + lane];
            } else {
                uint2 b2 = ((const uint2*)bbuf4)[ns * 32 + lane];
                bw[0] = b2.x; bw[1] = b2.y;
            }
#pragma unroll
            for (int nt = 0; nt < NT; nt++) {
                mma16(acc[0][nt], (const unsigned*)&av[0], bw[nt * 2], bw[nt * 2 + 1]);
                mma16(acc[1][nt], (const unsigned*)&av[1], bw[nt * 2], bw[nt * 2 + 1]);
            }
        }
    }
    if (PE) __syncthreads();             // in-place: all reads done before writes
#pragma unroll
    for (int mt = 0; mt < 2; mt++)
#pragma unroll
        for (int nt = 0; nt < NT; nt++)
            epi((mt0 + mt) * 16 + g, ncol + nt * 8 + tg * 2, acc[mt][nt]);
    __syncthreads();                     // publish epi writes; protect B bufs
}

// ---------------- main fused kernel (256 thr, 64 patches/CTA) ------------
__global__ void __launch_bounds__(256, 2) lista_mma(
    const float* __restrict__ x,  const float* __restrict__ cp,
    const float* __restrict__ wp,
    const float* __restrict__ b1, const float* __restrict__ b2,
    const float* __restrict__ b3, const float* __restrict__ W4,
    const float* __restrict__ b4)
{
    extern __shared__ float sm[];
    __half2* smh2 = (__half2*)sm;
    __half*  smh  = (__half*)sm;
    uint2*   ycu  = (uint2*)(sm + YC_OFF);
    const int tid = threadIdx.x;
    const int img = blockIdx.z;
    const int pr0 = blockIdx.y * 8, pc0 = blockIdx.x * 8;
    const float cv = cp[0], wv = wp[0];
    const float* xi = x + img * 16384;
    float* thr = sm + THR_OFF;

    // ---- U -> A frag cols [256,320), fp16, zero-padded outside image ----
    for (int idx = tid; idx < 4096; idx += 256) {
        int m = idx >> 6, d = idx & 63;
        int pr = pr0 + (m >> 3), pc = pc0 + (m & 7);
        float v = (pr < OH && pc < OH) ? xi[(pr + (d >> 3)) * 128 + pc + (d & 7)] : 0.0f;
        smh[af_half(m, 256 + d)] = __float2half_rn(v);
    }
    // (first barrier inside gemm_stage publishes U)

    // ---- h1 = relu(U@W1+b1) -> cols [0,128) ----
    gemm_stage<128, 64, 16, false>(sm, g_Bh1, tid, [&](int r, int c, float* d) {
        float bb0 = __ldg(b1 + c), bb1 = __ldg(b1 + c + 1);
        smh2[af_word(r, c)]     = __floats2half2_rn(fmaxf(d[0] + bb0, 0.0f),
                                                    fmaxf(d[1] + bb1, 0.0f));
        smh2[af_word(r + 8, c)] = __floats2half2_rn(fmaxf(d[2] + bb0, 0.0f),
                                                    fmaxf(d[3] + bb1, 0.0f));
    });

    // ---- h2 = relu(h1@W2+b2) -> cols [128,192) ----
    gemm_stage<64, 128, 0, false>(sm, g_Bh2, tid, [&](int r, int c, float* d) {
        float bb0 = __ldg(b2 + c), bb1 = __ldg(b2 + c + 1);
        int cc = 128 + c;
        smh2[af_word(r, cc)]     = __floats2half2_rn(fmaxf(d[0] + bb0, 0.0f),
                                                     fmaxf(d[1] + bb1, 0.0f));
        smh2[af_word(r + 8, cc)] = __floats2half2_rn(fmaxf(d[2] + bb0, 0.0f),
                                                     fmaxf(d[3] + bb1, 0.0f));
    });

    // ---- h3 = relu(h2@W3+b3) -> cols [192,224) ----
    gemm_stage<32, 64, 8, false>(sm, g_Bh3, tid, [&](int r, int c, float* d) {
        float bb0 = __ldg(b3 + c), bb1 = __ldg(b3 + c + 1);
        int cc = 192 + c;
        smh2[af_word(r, cc)]     = __floats2half2_rn(fmaxf(d[0] + bb0, 0.0f),
                                                     fmaxf(d[1] + bb1, 0.0f));
        smh2[af_word(r + 8, cc)] = __floats2half2_rn(fmaxf(d[2] + bb0, 0.0f),
                                                     fmaxf(d[3] + bb1, 0.0f));
    });

    // ---- thr[m] = (h3[m]@W4 + b4)/c  (h3 published by stage's trailing bar)
    if (tid < 64) {
        float a = b4[0];
#pragma unroll
        for (int j = 0; j < 32; j++)
            a = fmaf(__half2float(smh[af_half(tid, 192 + j)]), r16(__ldg(W4 + j)), a);
        thr[tid] = a / cv;
    }
    // (published by y-stage's first barrier; read only in y's epilogue)

    // ---- y = U@Dict ; yc = fp16(y/c) -> frag smem ; z0 = soft(y,thr) ----
    gemm_stage<256, 64, 16, false>(sm, g_By, tid, [&](int r, int c, float* d) {
        float t0 = thr[r], t1 = thr[r + 8];
        uint2 y2;
        y2.x = h2u(__floats2half2_rn(d[0] / cv, d[1] / cv));
        y2.y = h2u(__floats2half2_rn(d[2] / cv, d[3] / cv));
        ycu[yc_idx(r, c)] = y2;
        smh2[af_word(r, c)]     = __floats2half2_rn(softthr(d[0], t0), softthr(d[1], t0));
        smh2[af_word(r + 8, c)] = __floats2half2_rn(softthr(d[2], t1), softthr(d[3], t1));
    });

    // ---- 7x LISTA: z = soft(z@S + y/c, thr), K=256 (y/c from smem) ----
    for (int it = 0; it < 7; it++) {
        gemm_stage<256, 256, 0, true>(sm, g_Bls, tid, [&](int r, int c, float* d) {
            float t0 = thr[r], t1 = thr[r + 8];
            uint2 y2 = ycu[yc_idx(r, c)];
            __half2 ya = u2h(y2.x), yb = u2h(y2.y);
            float v0 = d[0] + __low2float(ya),  v1 = d[1] + __high2float(ya);
            float v2 = d[2] + __low2float(yb),  v3 = d[3] + __high2float(yb);
            smh2[af_word(r, c)]     = __floats2half2_rn(softthr(v0, t0), softthr(v1, t0));
            smh2[af_word(r + 8, c)] = __floats2half2_rn(softthr(v2, t1), softthr(v3, t1));
        });
    }

    // ---- x_pred = clip(z@Dict^T, 0, 1)*w -> g_XP ([d][img][pix] planes) ----
    gemm_stage<64, 256, 0, false>(sm, g_Bxp, tid, [&](int r, int c, float* d) {
        int pr = pr0 + (r >> 3), pc = pc0 + (r & 7);
        if (pr < OH && pc < OH) {
            int gp = img * 16384 + pr * 128 + pc;
            g_XP[(size_t)c * 131072 + gp]       = fminf(fmaxf(d[0], 0.0f), 1.0f) * wv;
            g_XP[(size_t)(c + 1) * 131072 + gp] = fminf(fmaxf(d[1], 0.0f), 1.0f) * wv;
        }
        int r2 = r + 8;
        int pr2 = pr0 + (r2 >> 3), pc2 = pc0 + (r2 & 7);
        if (pr2 < OH && pc2 < OH) {
            int gp2 = img * 16384 + pr2 * 128 + pc2;
            g_XP[(size_t)c * 131072 + gp2]       = fminf(fmaxf(d[2], 0.0f), 1.0f) * wv;
            g_XP[(size_t)(c + 1) * 131072 + gp2] = fminf(fmaxf(d[3], 0.0f), 1.0f) * wv;
        }
    });
}

// ---------------- prep: S (fp16, K16-chunk frag order) ----------------
__global__ void prep_S(const float* __restrict__ Dict, const float* __restrict__ cp) {
    int k = blockIdx.x, n = threadIdx.x;
    float c = cp[0], s = 0.0f;
#pragma unroll 8
    for (int r = 0; r < 64; r++)
        s = fmaf(r16(Dict[r * 256 + k]), r16(Dict[r * 256 + n]), s);
    g_Bls[fidx_h(256, k, n)] = __float2half_rn((k == n ? 1.0f : 0.0f) - s / c);
}

// ---------------- prep: all other B operands ----------------
__global__ void prep_misc(const float* __restrict__ Dict, const float* __restrict__ W1,
                          const float* __restrict__ W2, const float* __restrict__ W3) {
    int idx = blockIdx.x * 256 + threadIdx.x;     // 64 blocks -> 16384 ids
    if (idx < 16384) {
        int kk = idx >> 8, n = idx & 255;
        g_By[fidx_h(256, kk, n)] = __float2half_rn(Dict[idx]);
        int k2 = idx >> 6, n2 = idx & 63;
        g_Bxp[fidx_h(64, k2, n2)] = __float2half_rn(Dict[n2 * 256 + k2]);
    }
    if (idx < 8192) {
        g_Bh1[fidx_h(128, idx >> 7, idx & 127)] = __float2half_rn(W1[idx]);
        g_Bh2[fidx_h(64,  idx >> 6, idx & 63)]  = __float2half_rn(W2[idx]);
    }
    if (idx < 2048)
        g_Bh3[fidx_h(32, idx >> 5, idx & 31)] = __float2half_rn(W3[idx]);
}

// ---------------- finalize: coalesced gather fold + analytic denominator ----
__global__ void finalize_kernel(float* __restrict__ out, const float* __restrict__ wp) {
    int idx = blockIdx.x * 256 + threadIdx.x;
    int img = idx >> 14, i = (idx >> 7) & 127, j = idx & 127;
    int base = img * 16384;
    float s = 0.0f;
#pragma unroll
    for (int di = 0; di < 8; di++) {
        int pr = i - di;
        if (pr < 0 || pr >= OH) continue;
#pragma unroll
        for (int dj = 0; dj < 8; dj++) {
            int pc = j - dj;
            if (pc < 0 || pc >= OH) continue;
            s += g_XP[(size_t)(di * 8 + dj) * 131072 + base + pr * 128 + pc];
        }
    }
    int ci = min(min(i + 1, 8), 128 - i);
    int cj = min(min(j + 1, 8), 128 - j);
    out[idx] = s / (wp[0] * (float)(ci * cj));
}

// ---------------- launch ----------------
extern "C" void kernel_launch(void* const* d_in, const int* in_sizes, int n_in,
                              void* d_out, int out_size) {
    const float* x    = (const float*)d_in[0];
    const float* Dict = (const float*)d_in[1];
    const float* c    = (const float*)d_in[2];
    const float* w    = (const float*)d_in[3];
    const float* W1   = (const float*)d_in[4];
    const float* b1   = (const float*)d_in[5];
    const float* W2   = (const float*)d_in[6];
    const float* b2   = (const float*)d_in[7];
    const float* W3   = (const float*)d_in[8];
    const float* b3   = (const float*)d_in[9];
    const float* W4   = (const float*)d_in[10];
    const float* b4   = (const float*)d_in[11];
    float* out = (float*)d_out;

    cudaFuncSetAttribute(lista_mma, cudaFuncAttributeMaxDynamicSharedMemorySize, SMEM_BYTES);

    prep_S<<<256, 256>>>(Dict, c);
    prep_misc<<<64, 256>>>(Dict, W1, W2, W3);
    lista_mma<<<dim3(16, 16, NIMG), 256, SMEM_BYTES>>>(x, c, w, b1, b2, b3, W4, b4);
    finalize_kernel<<<512, 256>>>(out, w);
}